// round 1
// baseline (speedup 1.0000x reference)
#include <cuda_runtime.h>
#include <math.h>

#define NS   512
#define NU   64
#define DIM  1024
#define NROWS (NS*NU)          // 32768
#define EPSV 1e-6f

// ---------------- scratch (static device globals; no allocations) ----------
__device__ float  g_S[NS*DIM];        // speaker sums           [512,1024]  2 MiB
__device__ float  g_CnT[DIM*NS];      // normalized centroids, k-major [1024,512] 2 MiB
__device__ float  g_inv_e[NROWS];     // 1/||x_row||  (with EPS guard)
__device__ float  g_cos_self[NROWS];  // e . uc_norm  per row
__device__ double g_loss;

// ---------------- kernel 0: reset accumulator ------------------------------
__global__ void k_init() { g_loss = 0.0; }

// ---------------- kernel 1: centroids --------------------------------------
// grid 512 (one speaker per block), 256 threads; each thread owns 4 d's.
__global__ void k_centroid(const float* __restrict__ X) {
    int n = blockIdx.x;
    int t = threadIdx.x;
    const float* xn = X + (size_t)n * NU * DIM;
    float s0 = 0.f, s1 = 0.f, s2 = 0.f, s3 = 0.f;
    #pragma unroll 4
    for (int m = 0; m < NU; ++m) {
        const float* r = xn + m * DIM;
        s0 += r[t];
        s1 += r[t + 256];
        s2 += r[t + 512];
        s3 += r[t + 768];
    }
    float m0 = s0 * (1.f / NU), m1 = s1 * (1.f / NU);
    float m2 = s2 * (1.f / NU), m3 = s3 * (1.f / NU);
    float ssl = m0 * m0 + m1 * m1 + m2 * m2 + m3 * m3;

    __shared__ float red[256];
    red[t] = ssl;
    __syncthreads();
    for (int s = 128; s > 0; s >>= 1) {
        if (t < s) red[t] += red[t + s];
        __syncthreads();
    }
    float inv = rsqrtf(fmaxf(red[0], EPSV));

    g_S[(size_t)n * DIM + t      ] = s0;
    g_S[(size_t)n * DIM + t + 256] = s1;
    g_S[(size_t)n * DIM + t + 512] = s2;
    g_S[(size_t)n * DIM + t + 768] = s3;

    g_CnT[(size_t)(t      ) * NS + n] = m0 * inv;
    g_CnT[(size_t)(t + 256) * NS + n] = m1 * inv;
    g_CnT[(size_t)(t + 512) * NS + n] = m2 * inv;
    g_CnT[(size_t)(t + 768) * NS + n] = m3 * inv;
}

// ---------------- kernel 2: per-row norms + cos_self ------------------------
// grid 32768 (one (n,m) row per block), 128 threads.
// uc_vec = (S - x)/(M-1); normalization scale on uc cancels except through EPS,
// so keep the exact reference form: inv_u = rsqrt(max(ssu/63^2, EPS)).
__global__ void k_rows(const float* __restrict__ X) {
    int row = blockIdx.x;
    int n = row >> 6;
    const float* x = X + (size_t)row * DIM;
    const float* S = g_S + (size_t)n * DIM;
    float ssx = 0.f, ssu = 0.f, dxu = 0.f;
    for (int d = threadIdx.x; d < DIM; d += 128) {
        float xv = x[d];
        float uv = S[d] - xv;
        ssx += xv * xv;
        ssu += uv * uv;
        dxu += xv * uv;
    }
    #pragma unroll
    for (int o = 16; o > 0; o >>= 1) {
        ssx += __shfl_xor_sync(0xffffffffu, ssx, o);
        ssu += __shfl_xor_sync(0xffffffffu, ssu, o);
        dxu += __shfl_xor_sync(0xffffffffu, dxu, o);
    }
    __shared__ float rr[4][3];
    int w = threadIdx.x >> 5, l = threadIdx.x & 31;
    if (l == 0) { rr[w][0] = ssx; rr[w][1] = ssu; rr[w][2] = dxu; }
    __syncthreads();
    if (threadIdx.x == 0) {
        float a = rr[0][0] + rr[1][0] + rr[2][0] + rr[3][0];
        float u = rr[0][1] + rr[1][1] + rr[2][1] + rr[3][1];
        float c = rr[0][2] + rr[1][2] + rr[2][2] + rr[3][2];
        float inv_e = rsqrtf(fmaxf(a, EPSV));
        float inv_u = rsqrtf(fmaxf(u * (1.f / (63.f * 63.f)), EPSV));
        g_inv_e[row]    = inv_e;
        g_cos_self[row] = c * (1.f / 63.f) * inv_e * inv_u;
    }
}

// ---------------- kernel 3: GEMM (X . CnT) + LSE epilogue -------------------
// Block tile: 32 rows x 512 cols x K=1024. 256 threads.
// tr = tid/32 (8 row-groups of 4 rows), tc = tid%32 (16 cols each).
// One warp == one tr == 4 rows x all 512 cols -> warp-local LSE via shuffles.
// Inner product uses packed fma.rn.f32x2 (2 fp32 FMA / lane / instr).
#define BR 32
#define KC 16

__global__ __launch_bounds__(256, 2)
void k_gemm(const float* __restrict__ X,
            const float* __restrict__ wp,
            const float* __restrict__ bp) {
    __shared__ float  Xs[BR][KC + 4];      // row stride 20 floats (16B-aligned rows)
    __shared__ float4 Cs[KC][NS / 4];      // 16 x 128 float4 = 32 KiB

    int tid = threadIdx.x;
    int tr = tid >> 5;                     // 0..7
    int tc = tid & 31;                     // 0..31
    int r0 = blockIdx.x * BR;

    unsigned long long acc2[4][8];         // 4 rows x 8 col-pairs (16 cols)
    #pragma unroll
    for (int i = 0; i < 4; ++i)
        #pragma unroll
        for (int j = 0; j < 8; ++j) acc2[i][j] = 0ull;

    for (int k0 = 0; k0 < DIM; k0 += KC) {
        // load X tile: 32 rows x 16 floats = 128 float4
        if (tid < 128) {
            int r = tid >> 2, c4 = tid & 3;
            float4 v = *(const float4*)(X + (size_t)(r0 + r) * DIM + k0 + c4 * 4);
            *(float4*)&Xs[r][c4 * 4] = v;
        }
        // load C tile: 16 x 512 floats = 2048 float4, 8 per thread
        #pragma unroll
        for (int j = 0; j < 8; ++j) {
            int idx = tid + j * 256;       // 0..2047
            int kk = idx >> 7, c = idx & 127;
            Cs[kk][c] = *(const float4*)(g_CnT + (size_t)(k0 + kk) * NS + c * 4);
        }
        __syncthreads();

        #pragma unroll
        for (int kk = 0; kk < KC; ++kk) {
            unsigned long long a2[4];
            #pragma unroll
            for (int i = 0; i < 4; ++i) {
                float av = Xs[tr * 4 + i][kk];
                asm("mov.b64 %0, {%1, %1};" : "=l"(a2[i]) : "f"(av));
            }
            const double2* cp = (const double2*)(&Cs[kk][tc * 4]);
            #pragma unroll
            for (int q = 0; q < 4; ++q) {
                double2 dv = cp[q];
                unsigned long long clo = __double_as_longlong(dv.x);
                unsigned long long chi = __double_as_longlong(dv.y);
                #pragma unroll
                for (int i = 0; i < 4; ++i) {
                    asm("fma.rn.f32x2 %0, %1, %2, %0;"
                        : "+l"(acc2[i][2 * q    ]) : "l"(a2[i]), "l"(clo));
                    asm("fma.rn.f32x2 %0, %1, %2, %0;"
                        : "+l"(acc2[i][2 * q + 1]) : "l"(a2[i]), "l"(chi));
                }
            }
        }
        __syncthreads();
    }

    // ---- epilogue: sim = w*cos + b, diagonal -> cos_self, warp LSE ----
    const float wv = *wp, bv = *bp;
    double tsum = 0.0;
    #pragma unroll
    for (int i = 0; i < 4; ++i) {
        int row = r0 + tr * 4 + i;
        int n = row >> 6;
        float inv_e = g_inv_e[row];
        float pos = wv * g_cos_self[row] + bv;
        float sv[16];
        float mx = -3.0e38f;
        #pragma unroll
        for (int j = 0; j < 8; ++j) {
            unsigned lo, hi;
            asm("mov.b64 {%0, %1}, %2;" : "=r"(lo), "=r"(hi) : "l"(acc2[i][j]));
            int col = tc * 16 + 4 * (j >> 1) + 2 * (j & 1);
            float s0 = wv * (__uint_as_float(lo) * inv_e) + bv;
            float s1 = wv * (__uint_as_float(hi) * inv_e) + bv;
            if (col     == n) s0 = pos;
            if (col + 1 == n) s1 = pos;
            sv[2 * j]     = s0;
            sv[2 * j + 1] = s1;
            mx = fmaxf(mx, fmaxf(s0, s1));
        }
        #pragma unroll
        for (int o = 16; o > 0; o >>= 1)
            mx = fmaxf(mx, __shfl_xor_sync(0xffffffffu, mx, o));
        float se = 0.f;
        #pragma unroll
        for (int j = 0; j < 16; ++j) se += __expf(sv[j] - mx);
        #pragma unroll
        for (int o = 16; o > 0; o >>= 1)
            se += __shfl_xor_sync(0xffffffffu, se, o);
        if (tc == 0) tsum += (double)(mx + __logf(se) - pos);
    }

    __shared__ double dred[8];
    if (tc == 0) dred[tr] = tsum;
    __syncthreads();
    if (tid == 0) {
        double bs = 0.0;
        #pragma unroll
        for (int i = 0; i < 8; ++i) bs += dred[i];
        atomicAdd(&g_loss, bs);
    }
}

// ---------------- kernel 4: finalize ----------------------------------------
__global__ void k_fin(float* __restrict__ out) {
    out[0] = (float)g_loss;
}

// ---------------- launcher ---------------------------------------------------
extern "C" void kernel_launch(void* const* d_in, const int* in_sizes, int n_in,
                              void* d_out, int out_size) {
    const float* X = (const float*)d_in[0];
    const float* w = (const float*)d_in[1];
    const float* b = (const float*)d_in[2];
    float* out = (float*)d_out;

    k_init<<<1, 1>>>();
    k_centroid<<<NS, 256>>>(X);
    k_rows<<<NROWS, 128>>>(X);
    k_gemm<<<NROWS / BR, 256>>>(X, w, b);
    k_fin<<<1, 1>>>(out);
}

// round 3
// speedup vs baseline: 9.7877x; 9.7877x over previous
#include <cuda_runtime.h>
#include <cuda_bf16.h>
#include <stdint.h>

#define NS     512
#define NU     64
#define DIM    1024
#define NROWS  (NS*NU)         // 32768
#define EPSV   1e-6f
#define BM     128
#define BN     256
#define KC     64
#define NSTAGE (DIM/KC)        // 16
#define STG_BYTES 49152        // A 16KB + B 32KB (1KB-aligned)
#define NBUF   4
#define LOG2E  1.4426950408889634f
#define LN2    0.6931471805599453f
#define SMEM_DYN (NBUF*STG_BYTES + 1024 + 1024)

// ---------------- device scratch ----------------
__device__ __nv_bfloat16 g_Xb[(size_t)NROWS*DIM];   // 64 MB bf16 X
__device__ __nv_bfloat16 g_Cbf[NS*DIM];             // normalized centroids [n][d]
__device__ float  g_S[NS*DIM];                      // speaker sums
__device__ float  g_SS[NS];                         // ||S||^2
__device__ float  g_inv_e[NROWS];
__device__ float  g_cs[NROWS];                      // cos_self
__device__ float  g_ps[2*(size_t)NROWS];            // partial sum-of-exp2 per col-split
__device__ double g_loss;

// ---------------- helpers ----------------
__device__ __forceinline__ uint32_t smem_u32(const void* p) {
    uint32_t a;
    asm("{ .reg .u64 t; cvta.to.shared.u64 t, %1; cvt.u32.u64 %0, t; }"
        : "=r"(a) : "l"(p));
    return a;
}
#define CP_ASYNC(d, s) \
    asm volatile("cp.async.cg.shared.global [%0], [%1], 16;" :: "r"(d), "l"(s) : "memory")
#define CP_COMMIT asm volatile("cp.async.commit_group;" ::: "memory")
#define CP_WAIT2  asm volatile("cp.async.wait_group 2;" ::: "memory")
#define LDSM4(r0, r1, r2, r3, addr) \
    asm volatile("ldmatrix.sync.aligned.m8n8.x4.shared.b16 {%0,%1,%2,%3}, [%4];" \
        : "=r"(r0), "=r"(r1), "=r"(r2), "=r"(r3) : "r"(addr))
#define MMA(c, a, b0, b1) \
    asm volatile("mma.sync.aligned.m16n8k16.row.col.f32.bf16.bf16.f32 " \
        "{%0,%1,%2,%3},{%4,%5,%6,%7},{%8,%9},{%0,%1,%2,%3};" \
        : "+f"((c)[0]), "+f"((c)[1]), "+f"((c)[2]), "+f"((c)[3]) \
        : "r"((a)[0]), "r"((a)[1]), "r"((a)[2]), "r"((a)[3]), "r"(b0), "r"(b1))

// FMA-only 2^z (no MUFU): |z| <= ~64, rel err ~2e-6
__device__ __forceinline__ float exp2_fast(float z) {
    float kf = z + 12582912.0f;            // 1.5 * 2^23
    int   ki = __float_as_int(kf);
    float f  = z - (kf - 12582912.0f);     // f in [-0.5, 0.5]
    float p  = 1.33335581e-3f;
    p = fmaf(p, f, 9.61812910e-3f);
    p = fmaf(p, f, 5.55041087e-2f);
    p = fmaf(p, f, 2.40226507e-1f);
    p = fmaf(p, f, 6.93147181e-1f);
    p = fmaf(p, f, 1.0f);
    return __int_as_float(__float_as_int(p) + (ki << 23));
}

// ---------------- kernel 0: reset ----------------
__global__ void k_init() { g_loss = 0.0; }

// ---------------- kernel 1: centroids + X->bf16 ----------------
// grid 512, 256 threads; thread t owns cols 4t..4t+3 (one float4)
__global__ void k_centroid(const float* __restrict__ X) {
    int n = blockIdx.x, t = threadIdx.x;
    const float4* xn = (const float4*)(X + (size_t)n * NU * DIM);
    uint2* xb = (uint2*)(g_Xb + (size_t)n * NU * DIM);
    float4 s = make_float4(0.f, 0.f, 0.f, 0.f);
    #pragma unroll 4
    for (int m = 0; m < NU; ++m) {
        float4 v = xn[m * 256 + t];
        s.x += v.x; s.y += v.y; s.z += v.z; s.w += v.w;
        __nv_bfloat162 h0 = __float22bfloat162_rn(make_float2(v.x, v.y));
        __nv_bfloat162 h1 = __float22bfloat162_rn(make_float2(v.z, v.w));
        uint2 u; u.x = *(uint32_t*)&h0; u.y = *(uint32_t*)&h1;
        xb[m * 256 + t] = u;
    }
    float4 mn = make_float4(s.x * (1.f/NU), s.y * (1.f/NU),
                            s.z * (1.f/NU), s.w * (1.f/NU));
    float ssl = mn.x*mn.x + mn.y*mn.y + mn.z*mn.z + mn.w*mn.w;
    __shared__ float red[256];
    red[t] = ssl; __syncthreads();
    for (int o = 128; o > 0; o >>= 1) { if (t < o) red[t] += red[t + o]; __syncthreads(); }
    float inv = rsqrtf(fmaxf(red[0], EPSV));
    if (t == 0) g_SS[n] = red[0] * 4096.f;            // ||S||^2 = 64^2 * sum(mean^2)

    ((float4*)g_S)[n * 256 + t] = s;
    __nv_bfloat162 c0 = __float22bfloat162_rn(make_float2(mn.x*inv, mn.y*inv));
    __nv_bfloat162 c1 = __float22bfloat162_rn(make_float2(mn.z*inv, mn.w*inv));
    uint2 cu; cu.x = *(uint32_t*)&c0; cu.y = *(uint32_t*)&c1;
    ((uint2*)g_Cbf)[n * 256 + t] = cu;
}

// ---------------- kernel 2: per-row stats (fp32 exact) ----------------
__global__ void k_rows(const float* __restrict__ X) {
    int row = blockIdx.x, n = row >> 6, t = threadIdx.x;
    const float4* x  = (const float4*)(X + (size_t)row * DIM);
    const float4* sp = (const float4*)(g_S + (size_t)n * DIM);
    float rx = 0.f, rs = 0.f;
    #pragma unroll
    for (int q = 0; q < 2; ++q) {
        float4 v = x[t * 2 + q], c = sp[t * 2 + q];
        rx += v.x*v.x + v.y*v.y + v.z*v.z + v.w*v.w;
        rs += v.x*c.x + v.y*c.y + v.z*c.z + v.w*c.w;
    }
    #pragma unroll
    for (int o = 16; o > 0; o >>= 1) {
        rx += __shfl_xor_sync(0xffffffffu, rx, o);
        rs += __shfl_xor_sync(0xffffffffu, rs, o);
    }
    __shared__ float r2[4][2];
    int w = t >> 5, l = t & 31;
    if (l == 0) { r2[w][0] = rx; r2[w][1] = rs; }
    __syncthreads();
    if (t == 0) {
        float a = r2[0][0] + r2[1][0] + r2[2][0] + r2[3][0];
        float b = r2[0][1] + r2[1][1] + r2[2][1] + r2[3][1];
        float inv_e = rsqrtf(fmaxf(a, EPSV));
        float xu = (b - a) * (1.f / 63.f);
        float uu = (g_SS[n] - 2.f * b + a) * (1.f / 3969.f);
        g_inv_e[row] = inv_e;
        g_cs[row]    = xu * inv_e * rsqrtf(fmaxf(uu, EPSV));
    }
}

// ---------------- kernel 3: bf16 HMMA GEMM + partial softmax sums ----------
// grid (256, 2): 128 rows x 256 cols per CTA. 8 warps: 4 row x 2 col.
__global__ __launch_bounds__(256, 1)
void k_gemm(const float* __restrict__ wp, const float* __restrict__ bp) {
    extern __shared__ char smraw[];
    uint32_t raw  = smem_u32(smraw);
    uint32_t base = (raw + 1023u) & ~1023u;
    float* sm_s   = (float*)(smraw + (base - raw) + NBUF * STG_BYTES);

    int tid = threadIdx.x, lane = tid & 31, wid = tid >> 5;
    int wr = wid & 3, wc = wid >> 2;
    int r0 = blockIdx.x * BM, c0 = blockIdx.y * BN;

    float acc[2][16][4];
    #pragma unroll
    for (int i = 0; i < 2; ++i)
        #pragma unroll
        for (int j = 0; j < 16; ++j)
            #pragma unroll
            for (int q = 0; q < 4; ++q) acc[i][j][q] = 0.f;

    // ---- async loaders ----
    int arow_ld = tid >> 1, ahalf = tid & 1;
    const char* asrc0 = (const char*)(g_Xb + (size_t)(r0 + arow_ld) * DIM) + ahalf * 64;
    uint32_t ax = (uint32_t)(arow_ld & 7) * 16u;
    const char* bsrc0 = (const char*)(g_Cbf + (size_t)(c0 + tid) * DIM);
    uint32_t bx = (uint32_t)(tid & 7) * 16u;

    auto load_stage = [&](int s, int buf) {
        uint32_t sb = base + (uint32_t)buf * STG_BYTES;
        const char* as = asrc0 + (size_t)s * (KC * 2);
        uint32_t ad = sb + (uint32_t)arow_ld * 128u;
        #pragma unroll
        for (int q = 0; q < 4; ++q)
            CP_ASYNC(ad + (((uint32_t)(ahalf * 64 + q * 16)) ^ ax), as + q * 16);
        const char* bs = bsrc0 + (size_t)s * (KC * 2);
        uint32_t bd = sb + 16384u + (uint32_t)tid * 128u;
        #pragma unroll
        for (int q = 0; q < 8; ++q)
            CP_ASYNC(bd + (((uint32_t)(q * 16)) ^ bx), bs + q * 16);
    };

    // ---- mma over one staged KC=64 slab ----
    auto mma_stage = [&](int buf) {
        uint32_t ab = base + (uint32_t)buf * STG_BYTES;
        uint32_t bb = ab + 16384u;
        int arow = wr * 32 + (lane & 15);
        uint32_t aX = (uint32_t)(arow & 7) * 16u;
        uint32_t arb = ab + (uint32_t)arow * 128u;
        int nrl = wc * 128 + (lane & 7) + ((lane >> 4) << 3);
        uint32_t bX = (uint32_t)(lane & 7) * 16u;
        uint32_t brb = bb + (uint32_t)nrl * 128u;
        #pragma unroll
        for (int k16 = 0; k16 < 4; ++k16) {
            uint32_t acb = ((uint32_t)(k16 * 32 + ((lane >> 4) << 4))) ^ aX;
            uint32_t bcb = ((uint32_t)(k16 * 32 + (((lane >> 3) & 1) << 4))) ^ bX;
            uint32_t a[2][4];
            LDSM4(a[0][0], a[0][1], a[0][2], a[0][3], arb + acb);
            LDSM4(a[1][0], a[1][1], a[1][2], a[1][3], arb + 16u * 128u + acb);
            #pragma unroll
            for (int g = 0; g < 8; ++g) {
                uint32_t b0, b1, b2, b3;
                LDSM4(b0, b1, b2, b3, brb + (uint32_t)g * (16u * 128u) + bcb);
                MMA(acc[0][2 * g    ], a[0], b0, b1);
                MMA(acc[0][2 * g + 1], a[0], b2, b3);
                MMA(acc[1][2 * g    ], a[1], b0, b1);
                MMA(acc[1][2 * g + 1], a[1], b2, b3);
            }
        }
    };

    // ---- 4-deep pipeline ----
    load_stage(0, 0); CP_COMMIT;
    load_stage(1, 1); CP_COMMIT;
    load_stage(2, 2); CP_COMMIT;
    for (int s = 0; s < NSTAGE; ++s) {
        CP_WAIT2;
        __syncthreads();
        mma_stage(s & 3);
        if (s + 3 < NSTAGE) load_stage(s + 3, (s + 3) & 3);
        CP_COMMIT;
    }
    __syncthreads();

    // ---- epilogue: base-2 softmax partial sums (FMA-only exp) ----
    const float wv = *wp, bv = *bp;
    const float b2 = bv * LOG2E;
    #pragma unroll
    for (int mi = 0; mi < 2; ++mi)
        #pragma unroll
        for (int h = 0; h < 2; ++h) {
            int rl = wr * 32 + mi * 16 + (lane >> 2) + h * 8;
            int grow = r0 + rl, nself = grow >> 6;
            float scal2 = wv * g_inv_e[grow] * LOG2E;
            float zpos  = fmaf(wv * LOG2E, g_cs[grow], b2);
            float sum = 0.f;
            #pragma unroll
            for (int ni = 0; ni < 16; ++ni)
                #pragma unroll
                for (int j = 0; j < 2; ++j) {
                    int cg = c0 + wc * 128 + ni * 8 + (lane & 3) * 2 + j;
                    float z = fmaf(acc[mi][ni][h * 2 + j], scal2, b2);
                    if (cg == nself) z = zpos;
                    sum += exp2_fast(z);
                }
            sum += __shfl_xor_sync(0xffffffffu, sum, 1);
            sum += __shfl_xor_sync(0xffffffffu, sum, 2);
            if ((lane & 3) == 0) sm_s[wc * 128 + rl] = sum;
        }
    __syncthreads();
    if (tid < 128)
        g_ps[(size_t)blockIdx.y * NROWS + r0 + tid] = sm_s[tid] + sm_s[128 + tid];
}

// ---------------- kernel 4: combine + reduce loss ----------------
__global__ void k_fin2(const float* __restrict__ wp, const float* __restrict__ bp) {
    int row = blockIdx.x * 512 + threadIdx.x;
    float wv = *wp, bv = *bp;
    float S = g_ps[row] + g_ps[(size_t)NROWS + row];
    float pos = fmaf(wv, g_cs[row], bv);
    float c = LN2 * __log2f(S) - pos;
    #pragma unroll
    for (int o = 16; o > 0; o >>= 1) c += __shfl_xor_sync(0xffffffffu, c, o);
    __shared__ float rs[16];
    int w = threadIdx.x >> 5, l = threadIdx.x & 31;
    if (l == 0) rs[w] = c;
    __syncthreads();
    if (threadIdx.x == 0) {
        float bsum = 0.f;
        #pragma unroll
        for (int i = 0; i < 16; ++i) bsum += rs[i];
        atomicAdd(&g_loss, (double)bsum);
    }
}

__global__ void k_fin(float* __restrict__ out) { out[0] = (float)g_loss; }

// ---------------- launcher ----------------
extern "C" void kernel_launch(void* const* d_in, const int* in_sizes, int n_in,
                              void* d_out, int out_size) {
    const float* X = (const float*)d_in[0];
    const float* w = (const float*)d_in[1];
    const float* b = (const float*)d_in[2];
    float* out = (float*)d_out;

    cudaFuncSetAttribute(k_gemm, cudaFuncAttributeMaxDynamicSharedMemorySize, SMEM_DYN);

    k_init<<<1, 1>>>();
    k_centroid<<<NS, 256>>>(X);
    k_rows<<<NROWS, 128>>>(X);
    k_gemm<<<dim3(NROWS / BM, NS / BN), 256, SMEM_DYN>>>(w, b);
    k_fin2<<<NROWS / 512, 512>>>(w, b);
    k_fin<<<1, 1>>>(out);
}

// round 4
// speedup vs baseline: 12.4166x; 1.2686x over previous
#include <cuda_runtime.h>
#include <cuda_bf16.h>
#include <stdint.h>

#define NS     512
#define NU     64
#define DIM    1024
#define NROWS  (NS*NU)         // 32768
#define EPSV   1e-6f
#define BM     128
#define BN     256
#define KC     64
#define NSTAGE (DIM/KC)        // 16
#define STG_BYTES 49152        // A 16KB + B 32KB
#define NBUF   4
#define LOG2E  1.4426950408889634f
#define LN2    0.6931471805599453f
#define SMEM_DYN (NBUF*STG_BYTES + 1024 + 4096)

// ---------------- device scratch ----------------
__device__ __nv_bfloat16 g_Xb[(size_t)NROWS*DIM];   // 64 MB bf16 X
__device__ __nv_bfloat16 g_Cbf[NS*DIM];             // normalized centroids [n][d]
__device__ float  g_SS[NS];                         // ||S||^2
__device__ float  g_inv_e[NROWS];
__device__ float  g_cs[NROWS];                      // cos_self
__device__ float  g_ps[2*(size_t)NROWS];            // partial sum-of-exp2 per col-split
__device__ double g_loss;

// ---------------- helpers ----------------
__device__ __forceinline__ uint32_t smem_u32(const void* p) {
    uint32_t a;
    asm("{ .reg .u64 t; cvta.to.shared.u64 t, %1; cvt.u32.u64 %0, t; }"
        : "=r"(a) : "l"(p));
    return a;
}
#define CP_ASYNC(d, s) \
    asm volatile("cp.async.cg.shared.global [%0], [%1], 16;" :: "r"(d), "l"(s) : "memory")
#define CP_COMMIT asm volatile("cp.async.commit_group;" ::: "memory")
#define CP_WAIT2  asm volatile("cp.async.wait_group 2;" ::: "memory")
#define LDSM4(r0, r1, r2, r3, addr) \
    asm volatile("ldmatrix.sync.aligned.m8n8.x4.shared.b16 {%0,%1,%2,%3}, [%4];" \
        : "=r"(r0), "=r"(r1), "=r"(r2), "=r"(r3) : "r"(addr))
#define MMA(c, a, b0, b1) \
    asm volatile("mma.sync.aligned.m16n8k16.row.col.f32.bf16.bf16.f32 " \
        "{%0,%1,%2,%3},{%4,%5,%6,%7},{%8,%9},{%0,%1,%2,%3};" \
        : "+f"((c)[0]), "+f"((c)[1]), "+f"((c)[2]), "+f"((c)[3]) \
        : "r"((a)[0]), "r"((a)[1]), "r"((a)[2]), "r"((a)[3]), "r"(b0), "r"(b1))

// FMA-only 2^z (no MUFU): rel err ~2e-6
__device__ __forceinline__ float exp2_fast(float z) {
    float kf = z + 12582912.0f;            // 1.5 * 2^23
    int   ki = __float_as_int(kf);
    float f  = z - (kf - 12582912.0f);     // f in [-0.5, 0.5]
    float p  = 1.33335581e-3f;
    p = fmaf(p, f, 9.61812910e-3f);
    p = fmaf(p, f, 5.55041087e-2f);
    p = fmaf(p, f, 2.40226507e-1f);
    p = fmaf(p, f, 6.93147181e-1f);
    p = fmaf(p, f, 1.0f);
    return __int_as_float(__float_as_int(p) + (ki << 23));
}

// ---------------- kernel 0: reset ----------------
__global__ void k_init() { g_loss = 0.0; }

// ---------------- kernel 1: fused centroids + X->bf16 + per-row stats -------
// grid 512 (one speaker), 256 threads.
__global__ void k_prep(const float* __restrict__ X) {
    __shared__ float smS[DIM];       // speaker sum vector
    __shared__ float red[256];
    int n = blockIdx.x, t = threadIdx.x;
    const float4* xn = (const float4*)(X + (size_t)n * NU * DIM);
    uint2* xb = (uint2*)(g_Xb + (size_t)n * NU * DIM);

    // ---- phase 1: accumulate S, convert X to bf16 ----
    float4 s = make_float4(0.f, 0.f, 0.f, 0.f);
    #pragma unroll 4
    for (int m = 0; m < NU; ++m) {
        float4 v = xn[m * 256 + t];
        s.x += v.x; s.y += v.y; s.z += v.z; s.w += v.w;
        __nv_bfloat162 h0 = __float22bfloat162_rn(make_float2(v.x, v.y));
        __nv_bfloat162 h1 = __float22bfloat162_rn(make_float2(v.z, v.w));
        uint2 u; u.x = *(uint32_t*)&h0; u.y = *(uint32_t*)&h1;
        xb[m * 256 + t] = u;
    }
    float4 mn = make_float4(s.x * (1.f/NU), s.y * (1.f/NU),
                            s.z * (1.f/NU), s.w * (1.f/NU));
    float ssl = mn.x*mn.x + mn.y*mn.y + mn.z*mn.z + mn.w*mn.w;
    red[t] = ssl;
    ((float4*)smS)[t] = s;
    __syncthreads();
    for (int o = 128; o > 0; o >>= 1) { if (t < o) red[t] += red[t + o]; __syncthreads(); }
    float inv = rsqrtf(fmaxf(red[0], EPSV));
    float SS = red[0] * 4096.f;                       // ||S||^2 exact
    if (t == 0) g_SS[n] = SS;

    __nv_bfloat162 c0 = __float22bfloat162_rn(make_float2(mn.x*inv, mn.y*inv));
    __nv_bfloat162 c1 = __float22bfloat162_rn(make_float2(mn.z*inv, mn.w*inv));
    uint2 cu; cu.x = *(uint32_t*)&c0; cu.y = *(uint32_t*)&c1;
    ((uint2*)g_Cbf)[n * 256 + t] = cu;

    // ---- phase 2: per-row stats (X rows re-read from L2, S from shared) ----
    int wid = t >> 5, lane = t & 31;
    #pragma unroll 1
    for (int r = 0; r < 8; ++r) {
        int m = wid * 8 + r;
        const float4* x = xn + m * 256;
        float rx = 0.f, rs = 0.f;
        #pragma unroll
        for (int q = 0; q < 8; ++q) {
            float4 v = x[lane + 32 * q];
            float4 c = ((const float4*)smS)[lane + 32 * q];
            rx += v.x*v.x + v.y*v.y + v.z*v.z + v.w*v.w;
            rs += v.x*c.x + v.y*c.y + v.z*c.z + v.w*c.w;
        }
        #pragma unroll
        for (int o = 16; o > 0; o >>= 1) {
            rx += __shfl_xor_sync(0xffffffffu, rx, o);
            rs += __shfl_xor_sync(0xffffffffu, rs, o);
        }
        if (lane == 0) {
            int row = n * NU + m;
            float inv_e = rsqrtf(fmaxf(rx, EPSV));
            float xu = (rs - rx) * (1.f / 63.f);
            float uu = (SS - 2.f * rs + rx) * (1.f / 3969.f);
            g_inv_e[row] = inv_e;
            g_cs[row]    = xu * inv_e * rsqrtf(fmaxf(uu, EPSV));
        }
    }
}

// ---------------- kernel 2: bf16 HMMA GEMM + partial softmax sums ----------
// grid (256, 2): 128 rows x 256 cols per CTA. 16 warps: 4 row x 4 col (32x64).
__global__ __launch_bounds__(512, 1)
void k_gemm(const float* __restrict__ wp, const float* __restrict__ bp) {
    extern __shared__ char smraw[];
    uint32_t raw  = smem_u32(smraw);
    uint32_t base = (raw + 1023u) & ~1023u;
    float* sm_s   = (float*)(smraw + (base - raw) + NBUF * STG_BYTES);

    int tid = threadIdx.x, lane = tid & 31, wid = tid >> 5;
    int wr = wid & 3, wc = wid >> 2;     // 4 row-groups x 4 col-groups
    int r0 = blockIdx.x * BM, c0 = blockIdx.y * BN;

    float acc[2][8][4];
    #pragma unroll
    for (int i = 0; i < 2; ++i)
        #pragma unroll
        for (int j = 0; j < 8; ++j)
            #pragma unroll
            for (int q = 0; q < 4; ++q) acc[i][j][q] = 0.f;

    // ---- async loaders: A 16KB (2 chunks/thr), B 32KB (4 chunks/thr) ----
    int arow_ld = tid >> 2, ac = tid & 3;
    const char* asrc0 = (const char*)(g_Xb + (size_t)(r0 + arow_ld) * DIM) + ac * 16;
    uint32_t ax = (uint32_t)(arow_ld & 7) * 16u;
    uint32_t ad_base = (uint32_t)arow_ld * 128u;
    int brow_ld = tid >> 1, bc = tid & 1;
    const char* bsrc0 = (const char*)(g_Cbf + (size_t)(c0 + brow_ld) * DIM) + bc * 16;
    uint32_t bx = (uint32_t)(brow_ld & 7) * 16u;
    uint32_t bd_base = (uint32_t)brow_ld * 128u;

    auto load_stage = [&](int s, int buf) {
        uint32_t sb = base + (uint32_t)buf * STG_BYTES;
        const char* as = asrc0 + (size_t)s * (KC * 2);
        #pragma unroll
        for (int q = 0; q < 2; ++q)
            CP_ASYNC(sb + ad_base + (((uint32_t)(ac * 16 + q * 64)) ^ ax),
                     as + q * 64);
        const char* bs = bsrc0 + (size_t)s * (KC * 2);
        #pragma unroll
        for (int q = 0; q < 4; ++q)
            CP_ASYNC(sb + 16384u + bd_base + (((uint32_t)(bc * 16 + q * 32)) ^ bx),
                     bs + q * 32);
    };

    // ---- mma over one staged KC=64 slab ----
    auto mma_stage = [&](int buf) {
        uint32_t ab = base + (uint32_t)buf * STG_BYTES;
        uint32_t bb = ab + 16384u;
        int arow = wr * 32 + (lane & 15);
        uint32_t aX = (uint32_t)(arow & 7) * 16u;
        uint32_t arb = ab + (uint32_t)arow * 128u;
        int nrl = wc * 64 + (lane & 7) + ((lane >> 4) << 3);
        uint32_t bX = (uint32_t)(lane & 7) * 16u;
        uint32_t brb = bb + (uint32_t)nrl * 128u;
        #pragma unroll
        for (int k16 = 0; k16 < 4; ++k16) {
            uint32_t acb = ((uint32_t)(k16 * 32 + ((lane >> 4) << 4))) ^ aX;
            uint32_t bcb = ((uint32_t)(k16 * 32 + (((lane >> 3) & 1) << 4))) ^ bX;
            uint32_t a[2][4];
            LDSM4(a[0][0], a[0][1], a[0][2], a[0][3], arb + acb);
            LDSM4(a[1][0], a[1][1], a[1][2], a[1][3], arb + 16u * 128u + acb);
            #pragma unroll
            for (int g = 0; g < 4; ++g) {
                uint32_t b0, b1, b2, b3;
                LDSM4(b0, b1, b2, b3, brb + (uint32_t)g * (16u * 128u) + bcb);
                MMA(acc[0][2 * g    ], a[0], b0, b1);
                MMA(acc[0][2 * g + 1], a[0], b2, b3);
                MMA(acc[1][2 * g    ], a[1], b0, b1);
                MMA(acc[1][2 * g + 1], a[1], b2, b3);
            }
        }
    };

    // ---- 4-deep pipeline ----
    load_stage(0, 0); CP_COMMIT;
    load_stage(1, 1); CP_COMMIT;
    load_stage(2, 2); CP_COMMIT;
    for (int s = 0; s < NSTAGE; ++s) {
        CP_WAIT2;
        __syncthreads();
        mma_stage(s & 3);
        if (s + 3 < NSTAGE) load_stage(s + 3, (s + 3) & 3);
        CP_COMMIT;
    }
    __syncthreads();

    // ---- epilogue: base-2 softmax partial sums (FMA-only exp) ----
    const float wv = *wp, bv = *bp;
    const float b2 = bv * LOG2E;
    #pragma unroll
    for (int mi = 0; mi < 2; ++mi)
        #pragma unroll
        for (int h = 0; h < 2; ++h) {
            int rl = wr * 32 + mi * 16 + (lane >> 2) + h * 8;
            int grow = r0 + rl, nself = grow >> 6;
            float scal2 = wv * g_inv_e[grow] * LOG2E;
            float zpos  = fmaf(wv * LOG2E, g_cs[grow], b2);
            float sum = 0.f;
            #pragma unroll
            for (int ni = 0; ni < 8; ++ni)
                #pragma unroll
                for (int j = 0; j < 2; ++j) {
                    int cg = c0 + wc * 64 + ni * 8 + (lane & 3) * 2 + j;
                    float z = fmaf(acc[mi][ni][h * 2 + j], scal2, b2);
                    if (cg == nself) z = zpos;
                    sum += exp2_fast(z);
                }
            sum += __shfl_xor_sync(0xffffffffu, sum, 1);
            sum += __shfl_xor_sync(0xffffffffu, sum, 2);
            if ((lane & 3) == 0) sm_s[wc * 128 + rl] = sum;
        }
    __syncthreads();
    if (tid < 128)
        g_ps[(size_t)blockIdx.y * NROWS + r0 + tid] =
            (sm_s[tid] + sm_s[128 + tid]) + (sm_s[256 + tid] + sm_s[384 + tid]);
}

// ---------------- kernel 3: combine + reduce loss ----------------
__global__ void k_fin2(const float* __restrict__ wp, const float* __restrict__ bp) {
    int row = blockIdx.x * 512 + threadIdx.x;
    float wv = *wp, bv = *bp;
    float S = g_ps[row] + g_ps[(size_t)NROWS + row];
    float pos = fmaf(wv, g_cs[row], bv);
    float c = LN2 * __log2f(S) - pos;
    #pragma unroll
    for (int o = 16; o > 0; o >>= 1) c += __shfl_xor_sync(0xffffffffu, c, o);
    __shared__ float rs[16];
    int w = threadIdx.x >> 5, l = threadIdx.x & 31;
    if (l == 0) rs[w] = c;
    __syncthreads();
    if (threadIdx.x == 0) {
        float bsum = 0.f;
        #pragma unroll
        for (int i = 0; i < 16; ++i) bsum += rs[i];
        atomicAdd(&g_loss, (double)bsum);
    }
}

__global__ void k_fin(float* __restrict__ out) { out[0] = (float)g_loss; }

// ---------------- launcher ----------------
extern "C" void kernel_launch(void* const* d_in, const int* in_sizes, int n_in,
                              void* d_out, int out_size) {
    const float* X = (const float*)d_in[0];
    const float* w = (const float*)d_in[1];
    const float* b = (const float*)d_in[2];
    float* out = (float*)d_out;

    cudaFuncSetAttribute(k_gemm, cudaFuncAttributeMaxDynamicSharedMemorySize, SMEM_DYN);

    k_init<<<1, 1>>>();
    k_prep<<<NS, 256>>>(X);
    k_gemm<<<dim3(NROWS / BM, NS / BN), 512, SMEM_DYN>>>(w, b);
    k_fin2<<<NROWS / 512, 512>>>(w, b);
    k_fin<<<1, 1>>>(out);
}